// round 15
// baseline (speedup 1.0000x reference)
#include <cuda_runtime.h>
#include <cuda_fp16.h>
#include <math.h>
#include <stdint.h>

#define NN 100000
#define EE 1600000
#define HH 128
#define LL 5

// ---------------- device scratch (static; no allocations allowed) ----------
// fp16 activation slots: 0=input-layer out (x0), 1..4=conv0..3 out, 5=JK out
__device__ __align__(16) __half g_zh[6 * NN * HH];
__device__ __align__(16) __half g_h[NN * HH];       // gather output
__device__ __align__(16) uint8_t g_B[10 * 32768];   // fp16 W tiles (swizzled)
__device__ int   g_deg[NN];
__device__ int   g_rowptr[NN + 1];
__device__ int   g_cursor[NN];
__device__ int   g_col[EE];
__device__ int   g_is64;
__device__ int   g_part[128];
__device__ int   g_partoff[128];
__device__ float g_bnsum[3 * HH];   // per-layer slots, zeroed once in prologue
__device__ float g_bnsq[3 * HH];
__device__ float g_bns[HH];
__device__ float g_bnt[HH];

// ---------------- helpers ---------------------------------------------------
__device__ __forceinline__ uint32_t smem_u32(const void* p) {
    uint32_t a;
    asm("{ .reg .u64 t; cvta.to.shared.u64 t, %1; cvt.u32.u64 %0, t; }"
        : "=r"(a) : "l"(p));
    return a;
}

static __device__ __forceinline__ uint32_t pack_h2(float a, float b) {
    __half2 t = __floats2half2_rn(a, b);
    return *(uint32_t*)&t;
}

// XOR-swizzled byte offset inside a (rows x 128) fp16 tile (pitch 256B).
__device__ __forceinline__ int swz(int row, int col) {
    return row * 256 + ((((col >> 3) ^ (row & 7)) & 15) << 4) + ((col & 7) << 1);
}

#define LDMX4(r0, r1, r2, r3, addr) \
    asm volatile("ldmatrix.sync.aligned.m8n8.x4.shared.b16 {%0,%1,%2,%3}, [%4];" \
                 : "=r"(r0), "=r"(r1), "=r"(r2), "=r"(r3) : "r"(addr))

#define MMA16816H(c, a, b0, b1) \
    asm volatile( \
        "mma.sync.aligned.m16n8k16.row.col.f32.f16.f16.f32 " \
        "{%0,%1,%2,%3}, {%4,%5,%6,%7}, {%8,%9}, {%0,%1,%2,%3};" \
        : "+f"((c)[0]), "+f"((c)[1]), "+f"((c)[2]), "+f"((c)[3]) \
        : "r"((a)[0]), "r"((a)[1]), "r"((a)[2]), "r"((a)[3]), "r"(b0), "r"(b1))

// SMEM: A fp16 128x128 (32KB) + B fp16 (32KB) = 64KB
#define SM_A 0
#define SM_B 32768
#define SM_TOTAL 65536

// ---------------- B-tile preparation (once per launch) ----------------------
__global__ __launch_bounds__(256) void prep_b_k(
    const float* __restrict__ W_in, const float* __restrict__ convW,
    const float* __restrict__ W_jk,
    float b0, float b1, float b2, float b3, float b4) {
    int t = blockIdx.x;
    const float* W;
    float wscale;
    if (t == 0) { W = W_in; wscale = 1.f; }
    else if (t <= 5) {
        float blv = (t == 1) ? b0 : (t == 2) ? b1 : (t == 3) ? b2 : (t == 4) ? b3 : b4;
        W = convW + (long)(t - 1) * HH * HH;
        wscale = blv;
    } else { W = W_jk + (long)(t - 6) * HH * HH; wscale = 1.f; }

    int tid = threadIdx.x;
    int n = tid >> 1;
    int kb = (tid & 1) << 6;
    const float* Wb = W + (long)kb * HH + n;
    uint8_t* bp = g_B + (long)t * 32768;
    #pragma unroll
    for (int jj = 0; jj < 8; jj++) {
        int k0 = kb + jj * 8;
        uint4 hv;
        uint32_t* hp = &hv.x;
        #pragma unroll
        for (int q = 0; q < 4; q++) {
            float w0 = wscale * Wb[(long)(jj * 8 + q * 2) * HH];
            float w1 = wscale * Wb[(long)(jj * 8 + q * 2 + 1) * HH];
            hp[q] = pack_h2(w0, w1);
        }
        *(uint4*)(bp + swz(n, k0)) = hv;
    }
}

// ---------------- tensor-core GEMM (fp16 A, fp16 W, 1 term) -----------------
// MODE 0: single chunk +bias (A fp32 if HALFA=0).  MODE 1: plain conv.
// MODE 2: 4 chunks +bias.  IDENT 1: epilogue adds identc*h from A smem.
// STATS 1: atomicAdd col stats of final C into g_bnsum/g_bnsq at statoff.
template <int MODE, int STATS, int IDENT, int HALFA>
__global__ __launch_bounds__(256, 2) void gemm_tc_k(
    const void* __restrict__ A0, const void* __restrict__ A1,
    const void* __restrict__ A2, const void* __restrict__ A3,
    const float* __restrict__ bias, int tbase, float identc, int statoff,
    float* __restrict__ C, __half* __restrict__ Ch) {
    extern __shared__ char smem[];
    uint32_t sb = smem_u32(smem);
    const int tid = threadIdx.x;
    const int wid = tid >> 5, lane = tid & 31;
    const int block_row = blockIdx.x * 128;

    const int wm = (wid & 3) * 32;
    const int wn = (wid >> 2) * 64;
    const int lrow = lane & 7, quad = lane >> 3;

    float acc[2][8][4];
    #pragma unroll
    for (int i = 0; i < 2; i++)
        #pragma unroll
        for (int j = 0; j < 8; j++)
            #pragma unroll
            for (int q = 0; q < 4; q++) acc[i][j][q] = 0.f;

    const int NCH = (MODE == 2) ? 4 : 1;
    for (int c = 0; c < NCH; c++) {
        const void* Ab = (c == 0) ? A0 : (c == 1) ? A1 : (c == 2) ? A2 : A3;
        // ---- A tile fill ----
        {
            int row = tid >> 1;
            int cb = (tid & 1) << 6;
            int grow = block_row + row;
            #pragma unroll
            for (int jj = 0; jj < 8; jj++) {
                uint4 u = make_uint4(0u, 0u, 0u, 0u);
                if (grow < NN) {
                    if (HALFA) {
                        u = ((const uint4*)((const __half*)Ab + (long)grow * HH + cb))[jj];
                    } else {
                        const float4* sp = (const float4*)((const float*)Ab +
                                            (long)grow * HH + cb);
                        float4 v0 = sp[jj * 2], v1 = sp[jj * 2 + 1];
                        u.x = pack_h2(v0.x, v0.y);
                        u.y = pack_h2(v0.z, v0.w);
                        u.z = pack_h2(v1.x, v1.y);
                        u.w = pack_h2(v1.z, v1.w);
                    }
                }
                *(uint4*)(smem + SM_A + swz(row, cb + jj * 8)) = u;
            }
        }
        // ---- B tile fill: straight copy of preconverted swizzled image ----
        {
            const uint4* bsrc = (const uint4*)(g_B + (long)(tbase + c) * 32768);
            uint4* bdst = (uint4*)(smem + SM_B);
            #pragma unroll
            for (int s = tid; s < 2048; s += 256) bdst[s] = bsrc[s];
        }
        __syncthreads();

        // ---- compute: single fp16 term ----
        #pragma unroll
        for (int k16 = 0; k16 < 128; k16 += 16) {
            uint32_t a[2][4];
            #pragma unroll
            for (int mt = 0; mt < 2; mt++) {
                int row = wm + mt * 16 + (quad & 1) * 8 + lrow;
                int col = k16 + (quad >> 1) * 8;
                uint32_t addr = sb + SM_A + swz(row, col);
                LDMX4(a[mt][0], a[mt][1], a[mt][2], a[mt][3], addr);
            }
            #pragma unroll
            for (int nb = 0; nb < 4; nb++) {
                int row = wn + nb * 16 + (quad >> 1) * 8 + lrow;
                int col = k16 + (quad & 1) * 8;
                uint32_t addr = sb + SM_B + swz(row, col);
                uint32_t b0, b1, b2, b3;
                LDMX4(b0, b1, b2, b3, addr);
                #pragma unroll
                for (int mt = 0; mt < 2; mt++) {
                    MMA16816H(acc[mt][nb * 2], a[mt], b0, b1);
                    MMA16816H(acc[mt][nb * 2 + 1], a[mt], b2, b3);
                }
            }
        }
        __syncthreads();
    }

    // ---- epilogue: exact identity term from A smem (conv layers) ----
    if (IDENT) {
        #pragma unroll
        for (int mt = 0; mt < 2; mt++) {
            int row0 = wm + mt * 16 + (lane >> 2);
            int row1 = row0 + 8;
            #pragma unroll
            for (int nt = 0; nt < 8; nt++) {
                int cb = wn + nt * 8 + (lane & 3) * 2;
                __half2 h0 = *(__half2*)(smem + SM_A + swz(row0, cb));
                __half2 h1 = *(__half2*)(smem + SM_A + swz(row1, cb));
                float2 f0 = __half22float2(h0);
                float2 f1 = __half22float2(h1);
                acc[mt][nt][0] += identc * f0.x;
                acc[mt][nt][1] += identc * f0.y;
                acc[mt][nt][2] += identc * f1.x;
                acc[mt][nt][3] += identc * f1.y;
            }
        }
    }

    // ---- epilogue: store fp32 and/or fp16 ----
    #pragma unroll
    for (int mt = 0; mt < 2; mt++) {
        int r0 = block_row + wm + mt * 16 + (lane >> 2);
        int r1 = r0 + 8;
        #pragma unroll
        for (int nt = 0; nt < 8; nt++) {
            int cb = wn + nt * 8 + (lane & 3) * 2;
            float2 p0, p1;
            p0.x = acc[mt][nt][0]; p0.y = acc[mt][nt][1];
            p1.x = acc[mt][nt][2]; p1.y = acc[mt][nt][3];
            if (MODE != 1) {
                float bx = bias[cb], by = bias[cb + 1];
                p0.x += bx; p0.y += by;
                p1.x += bx; p1.y += by;
            }
            if (r0 < NN) {
                if (C)  *(float2*)(C + (long)r0 * HH + cb) = p0;
                if (Ch) *(uint32_t*)(Ch + (long)r0 * HH + cb) = pack_h2(p0.x, p0.y);
            }
            if (r1 < NN) {
                if (C)  *(float2*)(C + (long)r1 * HH + cb) = p1;
                if (Ch) *(uint32_t*)(Ch + (long)r1 * HH + cb) = pack_h2(p1.x, p1.y);
            }
        }
    }
    // ---- epilogue: fused BN statistics (after ident; padded rows = 0) ----
    if (STATS) {
        #pragma unroll
        for (int nt = 0; nt < 8; nt++) {
            #pragma unroll
            for (int p = 0; p < 2; p++) {
                float a00 = acc[0][nt][p],     a01 = acc[0][nt][2 + p];
                float a10 = acc[1][nt][p],     a11 = acc[1][nt][2 + p];
                float s = (a00 + a01) + (a10 + a11);
                float q = a00 * a00 + a01 * a01 + a10 * a10 + a11 * a11;
                #pragma unroll
                for (int m = 4; m < 32; m <<= 1) {
                    s += __shfl_xor_sync(0xFFFFFFFFu, s, m);
                    q += __shfl_xor_sync(0xFFFFFFFFu, q, m);
                }
                if (lane < 4) {
                    int cb = wn + nt * 8 + lane * 2 + p;
                    atomicAdd(&g_bnsum[statoff + cb], s);
                    atomicAdd(&g_bnsq[statoff + cb], q);
                }
            }
        }
    }
}

// ---------------- edge-list helpers ----------------------------------------
__device__ __forceinline__ int edge_at(const void* buf, int e) {
    if (g_is64) return (int)((const long long*)buf)[e];
    return ((const int*)buf)[e];
}

__global__ void detect64_k(const void* srcbuf) {
    const unsigned int* p = (const unsigned int*)srcbuf;
    int any = 0;
    for (int i = 1; i < 512; i += 2) any |= (p[i] != 0u);
    g_is64 = any ? 0 : 1;
}

// zero CSR arrays + all BN accumulator slots
__global__ void zero_all_k() {
    int i = blockIdx.x * blockDim.x + threadIdx.x;
    if (i < NN) { g_deg[i] = 0; g_cursor[i] = 0; }
    if (i < 3 * HH) { g_bnsum[i] = 0.f; g_bnsq[i] = 0.f; }
}

__global__ void hist_k(const void* dstbuf) {
    for (int e = blockIdx.x * blockDim.x + threadIdx.x; e < EE;
         e += gridDim.x * blockDim.x) {
        atomicAdd(&g_deg[edge_at(dstbuf, e)], 1);
    }
}

__global__ void scanA_k() {
    __shared__ int wt[32];
    int tid = threadIdx.x, lane = tid & 31, wid = tid >> 5;
    int i = blockIdx.x * 1024 + tid;
    int v = (i < NN) ? g_deg[i] : 0;
    int x = v;
    #pragma unroll
    for (int d = 1; d < 32; d <<= 1) {
        int y = __shfl_up_sync(0xFFFFFFFFu, x, d);
        if (lane >= d) x += y;
    }
    if (lane == 31) wt[wid] = x;
    __syncthreads();
    if (wid == 0) {
        int t = wt[lane];
        int tx = t;
        #pragma unroll
        for (int d = 1; d < 32; d <<= 1) {
            int y = __shfl_up_sync(0xFFFFFFFFu, tx, d);
            if (lane >= d) tx += y;
        }
        wt[lane] = tx - t;
    }
    __syncthreads();
    int incl = x + wt[wid];
    if (i < NN) g_rowptr[i] = incl - v;
    if (tid == 1023) g_part[blockIdx.x] = incl;
}

// parallel scan of the 98 block partials (1 block, 128 threads)
__global__ void scanB_k(int nblk) {
    __shared__ int wt[4];
    int tid = threadIdx.x, lane = tid & 31, wid = tid >> 5;
    int v = (tid < nblk) ? g_part[tid] : 0;
    int x = v;
    #pragma unroll
    for (int d = 1; d < 32; d <<= 1) {
        int y = __shfl_up_sync(0xFFFFFFFFu, x, d);
        if (lane >= d) x += y;
    }
    if (lane == 31) wt[wid] = x;
    __syncthreads();
    int woff = 0;
    for (int w = 0; w < wid; w++) woff += wt[w];
    int incl = x + woff;
    if (tid < nblk) g_partoff[tid] = incl - v;
    if (tid == 127) g_rowptr[NN] = incl;
}

__global__ void scanC_k() {
    int i = blockIdx.x * 1024 + threadIdx.x;
    if (i < NN) g_rowptr[i] += g_partoff[blockIdx.x];
}

__global__ void fill_k(const void* srcbuf, const void* dstbuf) {
    for (int e = blockIdx.x * blockDim.x + threadIdx.x; e < EE;
         e += gridDim.x * blockDim.x) {
        int d = edge_at(dstbuf, e);
        int s = edge_at(srcbuf, e);
        int pos = atomicAdd(&g_cursor[d], 1);
        g_col[g_rowptr[d] + pos] = s;
    }
}

// ------ gather: h = 0.9 * sum_src f(zh[src]) + 0.1 * x0h   (all fp16 I/O) ---
// 2 rows per warp, 16 lanes x 16B per row (LDG.128 per edge per lane).
// BNMODE 0: f = identity.  BNMODE 1: f(v) = relu(v * s[c] + t[c]).
template <int BNMODE>
__global__ void gather_k(const __half* __restrict__ zh,
                         const __half* __restrict__ x0h,
                         __half* __restrict__ h) {
    int warp = (blockIdx.x * blockDim.x + threadIdx.x) >> 5;
    int lane = threadIdx.x & 31;
    int sub = lane >> 4;       // half-warp: 0 or 1
    int sl = lane & 15;        // lane within half-warp
    int row = warp * 2 + sub;
    if (row >= NN) return;

    float s[8], t[8];
    if (BNMODE) {
        float4 sa = *(const float4*)(g_bns + sl * 8);
        float4 sb = *(const float4*)(g_bns + sl * 8 + 4);
        float4 ta = *(const float4*)(g_bnt + sl * 8);
        float4 tb = *(const float4*)(g_bnt + sl * 8 + 4);
        s[0] = sa.x; s[1] = sa.y; s[2] = sa.z; s[3] = sa.w;
        s[4] = sb.x; s[5] = sb.y; s[6] = sb.z; s[7] = sb.w;
        t[0] = ta.x; t[1] = ta.y; t[2] = ta.z; t[3] = ta.w;
        t[4] = tb.x; t[5] = tb.y; t[6] = tb.z; t[7] = tb.w;
    }

    int beg = g_rowptr[row], end = g_rowptr[row + 1];
    float acc[8];
    #pragma unroll
    for (int q = 0; q < 8; q++) acc[q] = 0.f;

    #define ACC16(u) do { \
        __half2* _h2 = (__half2*)&(u); \
        float2 _f[4]; \
        _f[0] = __half22float2(_h2[0]); _f[1] = __half22float2(_h2[1]); \
        _f[2] = __half22float2(_h2[2]); _f[3] = __half22float2(_h2[3]); \
        float _v[8] = {_f[0].x, _f[0].y, _f[1].x, _f[1].y, \
                       _f[2].x, _f[2].y, _f[3].x, _f[3].y}; \
        _Pragma("unroll") \
        for (int q = 0; q < 8; q++) { \
            float _x = _v[q]; \
            if (BNMODE) _x = fmaxf(fmaf(_x, s[q], t[q]), 0.f); \
            acc[q] += _x; \
        } } while (0)

    int e = beg;
    for (; e + 3 < end; e += 4) {
        int s0 = g_col[e], s1 = g_col[e + 1], s2 = g_col[e + 2], s3 = g_col[e + 3];
        uint4 u0 = ((const uint4*)(zh + (long)s0 * HH))[sl];
        uint4 u1 = ((const uint4*)(zh + (long)s1 * HH))[sl];
        uint4 u2 = ((const uint4*)(zh + (long)s2 * HH))[sl];
        uint4 u3 = ((const uint4*)(zh + (long)s3 * HH))[sl];
        ACC16(u0); ACC16(u1); ACC16(u2); ACC16(u3);
    }
    for (; e < end; ++e) {
        uint4 u = ((const uint4*)(zh + (long)g_col[e] * HH))[sl];
        ACC16(u);
    }
    #undef ACC16

    uint4 xu = ((const uint4*)(x0h + (long)row * HH))[sl];
    __half2* xh2 = (__half2*)&xu;
    float2 xf0 = __half22float2(xh2[0]);
    float2 xf1 = __half22float2(xh2[1]);
    float2 xf2 = __half22float2(xh2[2]);
    float2 xf3 = __half22float2(xh2[3]);
    float xv[8] = {xf0.x, xf0.y, xf1.x, xf1.y, xf2.x, xf2.y, xf3.x, xf3.y};

    uint4 o;
    uint32_t* op = &o.x;
    #pragma unroll
    for (int q = 0; q < 4; q++) {
        float a0 = 0.9f * acc[q * 2]     + 0.1f * xv[q * 2];
        float a1 = 0.9f * acc[q * 2 + 1] + 0.1f * xv[q * 2 + 1];
        op[q] = pack_h2(a0, a1);
    }
    ((uint4*)(h + (long)row * HH))[sl] = o;
}

// ---------------- BatchNorm finalize ----------------------------------------
__global__ void finalize_bn_k(const float* __restrict__ gamma,
                              const float* __restrict__ beta, int statoff) {
    int c = threadIdx.x;
    float invN = 1.0f / (float)NN;
    float m = g_bnsum[statoff + c] * invN;
    float var = g_bnsq[statoff + c] * invN - m * m;
    float s = rsqrtf(var + 1e-5f) * gamma[c];
    g_bns[c] = s;
    g_bnt[c] = beta[c] - m * s;
}

// ---------------- host orchestration ----------------------------------------
extern "C" void kernel_launch(void* const* d_in, const int* in_sizes, int n_in,
                              void* d_out, int out_size) {
    const float* x     = (const float*)d_in[0];
    const float* W_in  = (const float*)d_in[1];
    const float* b_in  = (const float*)d_in[2];
    const float* convW = (const float*)d_in[3];
    const float* gma   = (const float*)d_in[4];
    const float* bta   = (const float*)d_in[5];
    const float* W_jk  = (const float*)d_in[6];
    const float* b_jk  = (const float*)d_in[7];
    const void*  src   = d_in[8];
    const void*  dst   = d_in[9];
    float* out = (float*)d_out;

    void *ph, *pzh;
    cudaGetSymbolAddress(&ph, g_h);
    cudaGetSymbolAddress(&pzh, g_zh);
    __half* h   = (__half*)ph;
    __half* zh0 = (__half*)pzh;
    __half* zh1 = zh0 + (long)NN * HH;
    __half* zh2 = zh1 + (long)NN * HH;
    __half* zh3 = zh2 + (long)NN * HH;
    __half* zh4 = zh3 + (long)NN * HH;
    __half* zh5 = zh4 + (long)NN * HH;

    float bl[LL];
    for (int i = 0; i < LL; i++) bl[i] = (float)log(0.5 / (double)(i + 1) + 1.0);

    cudaFuncSetAttribute(gemm_tc_k<0, 0, 0, 0>, cudaFuncAttributeMaxDynamicSharedMemorySize, SM_TOTAL);
    cudaFuncSetAttribute(gemm_tc_k<1, 0, 1, 1>, cudaFuncAttributeMaxDynamicSharedMemorySize, SM_TOTAL);
    cudaFuncSetAttribute(gemm_tc_k<1, 1, 1, 1>, cudaFuncAttributeMaxDynamicSharedMemorySize, SM_TOTAL);
    cudaFuncSetAttribute(gemm_tc_k<2, 0, 0, 1>, cudaFuncAttributeMaxDynamicSharedMemorySize, SM_TOTAL);

    const int GEMM_BLOCKS = (NN + 127) / 128;            // 782
    const int GATHER_BLOCKS = ((NN + 1) / 2 * 32 + 255) / 256;
    const int SCAN_BLOCKS = (NN + 1023) / 1024;          // 98

    // ---- forked side stream: CSR build concurrent with prep + input GEMM ----
    cudaStream_t s2;
    cudaStreamCreateWithFlags(&s2, cudaStreamNonBlocking);
    cudaEvent_t evFork, evJoin;
    cudaEventCreateWithFlags(&evFork, cudaEventDisableTiming);
    cudaEventCreateWithFlags(&evJoin, cudaEventDisableTiming);

    cudaEventRecord(evFork, 0);
    cudaStreamWaitEvent(s2, evFork, 0);

    zero_all_k<<<(NN + 255) / 256, 256, 0, s2>>>();
    detect64_k<<<1, 1, 0, s2>>>(src);
    hist_k<<<1024, 256, 0, s2>>>(dst);
    scanA_k<<<SCAN_BLOCKS, 1024, 0, s2>>>();
    scanB_k<<<1, 128, 0, s2>>>(SCAN_BLOCKS);
    scanC_k<<<SCAN_BLOCKS, 1024, 0, s2>>>();
    fill_k<<<1024, 256, 0, s2>>>(src, dst);
    cudaEventRecord(evJoin, s2);

    // main stream: B prep + input GEMM (fp32 A, converts in fill)
    prep_b_k<<<10, 256>>>(W_in, convW, W_jk, bl[0], bl[1], bl[2], bl[3], bl[4]);
    gemm_tc_k<0, 0, 0, 0><<<GEMM_BLOCKS, 256, SM_TOTAL>>>(x, 0, 0, 0, b_in, 0,
                                                          0.f, 0, 0, zh0);

    cudaStreamWaitEvent(0, evJoin, 0);

    const __half* gin[LL]  = {zh0, zh1, zh2, zh3, zh5};
    __half* chout[LL]      = {zh1, zh2, zh3, zh4, 0};
    for (int i = 0; i < LL; i++) {
        if (i >= 1 && i <= 3)
            gather_k<1><<<GATHER_BLOCKS, 256>>>(gin[i], zh0, h);
        else
            gather_k<0><<<GATHER_BLOCKS, 256>>>(gin[i], zh0, h);
        float* Cout = (i == 4) ? out : 0;
        float identc = 1.0f - bl[i];
        if (i < 3) {
            gemm_tc_k<1, 1, 1, 1><<<GEMM_BLOCKS, 256, SM_TOTAL>>>(
                h, 0, 0, 0, 0, 1 + i, identc, i * HH, Cout, chout[i]);
            finalize_bn_k<<<1, HH>>>(gma + i * HH, bta + i * HH, i * HH);
        } else {
            gemm_tc_k<1, 0, 1, 1><<<GEMM_BLOCKS, 256, SM_TOTAL>>>(
                h, 0, 0, 0, 0, 1 + i, identc, 0, Cout, chout[i]);
        }
        if (i == 3) {
            gemm_tc_k<2, 0, 0, 1><<<GEMM_BLOCKS, 256, SM_TOTAL>>>(
                zh1, zh2, zh3, zh4, b_jk, 6, 0.f, 0, 0, zh5);
        }
    }

    cudaEventDestroy(evFork);
    cudaEventDestroy(evJoin);
    cudaStreamDestroy(s2);
    (void)in_sizes; (void)n_in; (void)out_size;
}

// round 16
// speedup vs baseline: 1.0032x; 1.0032x over previous
#include <cuda_runtime.h>
#include <cuda_fp16.h>
#include <math.h>
#include <stdint.h>

#define NN 100000
#define EE 1600000
#define HH 128
#define LL 5

// ---------------- device scratch (static; no allocations allowed) ----------
// fp16 activation slots: 0=input-layer out (x0), 1..4=conv0..3 out, 5=JK out
__device__ __align__(16) __half g_zh[6 * NN * HH];
__device__ __align__(16) __half g_h[NN * HH];       // gather output
__device__ __align__(16) uint8_t g_B[10 * 32768];   // fp16 W tiles (swizzled)
__device__ int   g_deg[NN];
__device__ int   g_rowptr[NN + 1];
__device__ int   g_cursor[NN];
__device__ int   g_col[EE];
__device__ int   g_is64;
__device__ int   g_part[128];
__device__ int   g_partoff[128];
__device__ float g_bnsum[3 * HH];   // per-layer slots, zeroed once in prologue
__device__ float g_bnsq[3 * HH];
__device__ float g_bns[HH];
__device__ float g_bnt[HH];

// ---------------- helpers ---------------------------------------------------
__device__ __forceinline__ uint32_t smem_u32(const void* p) {
    uint32_t a;
    asm("{ .reg .u64 t; cvta.to.shared.u64 t, %1; cvt.u32.u64 %0, t; }"
        : "=r"(a) : "l"(p));
    return a;
}

static __device__ __forceinline__ uint32_t pack_h2(float a, float b) {
    __half2 t = __floats2half2_rn(a, b);
    return *(uint32_t*)&t;
}

// XOR-swizzled byte offset inside a (rows x 128) fp16 tile (pitch 256B).
__device__ __forceinline__ int swz(int row, int col) {
    return row * 256 + ((((col >> 3) ^ (row & 7)) & 15) << 4) + ((col & 7) << 1);
}

#define LDMX4(r0, r1, r2, r3, addr) \
    asm volatile("ldmatrix.sync.aligned.m8n8.x4.shared.b16 {%0,%1,%2,%3}, [%4];" \
                 : "=r"(r0), "=r"(r1), "=r"(r2), "=r"(r3) : "r"(addr))

#define MMA16816H(c, a, b0, b1) \
    asm volatile( \
        "mma.sync.aligned.m16n8k16.row.col.f32.f16.f16.f32 " \
        "{%0,%1,%2,%3}, {%4,%5,%6,%7}, {%8,%9}, {%0,%1,%2,%3};" \
        : "+f"((c)[0]), "+f"((c)[1]), "+f"((c)[2]), "+f"((c)[3]) \
        : "r"((a)[0]), "r"((a)[1]), "r"((a)[2]), "r"((a)[3]), "r"(b0), "r"(b1))

// SMEM: A fp16 128x128 (32KB) + B fp16 (32KB) = 64KB
#define SM_A 0
#define SM_B 32768
#define SM_TOTAL 65536

// ---------------- B-tile preparation (once per launch) ----------------------
__global__ __launch_bounds__(256) void prep_b_k(
    const float* __restrict__ W_in, const float* __restrict__ convW,
    const float* __restrict__ W_jk,
    float b0, float b1, float b2, float b3, float b4) {
    int t = blockIdx.x;
    const float* W;
    float wscale;
    if (t == 0) { W = W_in; wscale = 1.f; }
    else if (t <= 5) {
        float blv = (t == 1) ? b0 : (t == 2) ? b1 : (t == 3) ? b2 : (t == 4) ? b3 : b4;
        W = convW + (long)(t - 1) * HH * HH;
        wscale = blv;
    } else { W = W_jk + (long)(t - 6) * HH * HH; wscale = 1.f; }

    int tid = threadIdx.x;
    int n = tid >> 1;
    int kb = (tid & 1) << 6;
    const float* Wb = W + (long)kb * HH + n;
    uint8_t* bp = g_B + (long)t * 32768;
    #pragma unroll
    for (int jj = 0; jj < 8; jj++) {
        int k0 = kb + jj * 8;
        uint4 hv;
        uint32_t* hp = &hv.x;
        #pragma unroll
        for (int q = 0; q < 4; q++) {
            float w0 = wscale * Wb[(long)(jj * 8 + q * 2) * HH];
            float w1 = wscale * Wb[(long)(jj * 8 + q * 2 + 1) * HH];
            hp[q] = pack_h2(w0, w1);
        }
        *(uint4*)(bp + swz(n, k0)) = hv;
    }
}

// ---------------- tensor-core GEMM (fp16 A, fp16 W, 1 term) -----------------
// MODE 0: single chunk +bias (A fp32 if HALFA=0).  MODE 1: plain conv.
// MODE 2: 4 chunks +bias.  IDENT 1: epilogue adds identc*h from A smem.
// STATS 1: atomicAdd col stats of final C into g_bnsum/g_bnsq at statoff.
template <int MODE, int STATS, int IDENT, int HALFA>
__global__ __launch_bounds__(256, 2) void gemm_tc_k(
    const void* __restrict__ A0, const void* __restrict__ A1,
    const void* __restrict__ A2, const void* __restrict__ A3,
    const float* __restrict__ bias, int tbase, float identc, int statoff,
    float* __restrict__ C, __half* __restrict__ Ch) {
    extern __shared__ char smem[];
    uint32_t sb = smem_u32(smem);
    const int tid = threadIdx.x;
    const int wid = tid >> 5, lane = tid & 31;
    const int block_row = blockIdx.x * 128;

    const int wm = (wid & 3) * 32;
    const int wn = (wid >> 2) * 64;
    const int lrow = lane & 7, quad = lane >> 3;

    float acc[2][8][4];
    #pragma unroll
    for (int i = 0; i < 2; i++)
        #pragma unroll
        for (int j = 0; j < 8; j++)
            #pragma unroll
            for (int q = 0; q < 4; q++) acc[i][j][q] = 0.f;

    const int NCH = (MODE == 2) ? 4 : 1;
    for (int c = 0; c < NCH; c++) {
        const void* Ab = (c == 0) ? A0 : (c == 1) ? A1 : (c == 2) ? A2 : A3;
        // ---- A tile fill ----
        {
            int row = tid >> 1;
            int cb = (tid & 1) << 6;
            int grow = block_row + row;
            #pragma unroll
            for (int jj = 0; jj < 8; jj++) {
                uint4 u = make_uint4(0u, 0u, 0u, 0u);
                if (grow < NN) {
                    if (HALFA) {
                        u = ((const uint4*)((const __half*)Ab + (long)grow * HH + cb))[jj];
                    } else {
                        const float4* sp = (const float4*)((const float*)Ab +
                                            (long)grow * HH + cb);
                        float4 v0 = sp[jj * 2], v1 = sp[jj * 2 + 1];
                        u.x = pack_h2(v0.x, v0.y);
                        u.y = pack_h2(v0.z, v0.w);
                        u.z = pack_h2(v1.x, v1.y);
                        u.w = pack_h2(v1.z, v1.w);
                    }
                }
                *(uint4*)(smem + SM_A + swz(row, cb + jj * 8)) = u;
            }
        }
        // ---- B tile fill: straight copy of preconverted swizzled image ----
        {
            const uint4* bsrc = (const uint4*)(g_B + (long)(tbase + c) * 32768);
            uint4* bdst = (uint4*)(smem + SM_B);
            #pragma unroll
            for (int s = tid; s < 2048; s += 256) bdst[s] = bsrc[s];
        }
        __syncthreads();

        // ---- compute: single fp16 term ----
        #pragma unroll
        for (int k16 = 0; k16 < 128; k16 += 16) {
            uint32_t a[2][4];
            #pragma unroll
            for (int mt = 0; mt < 2; mt++) {
                int row = wm + mt * 16 + (quad & 1) * 8 + lrow;
                int col = k16 + (quad >> 1) * 8;
                uint32_t addr = sb + SM_A + swz(row, col);
                LDMX4(a[mt][0], a[mt][1], a[mt][2], a[mt][3], addr);
            }
            #pragma unroll
            for (int nb = 0; nb < 4; nb++) {
                int row = wn + nb * 16 + (quad >> 1) * 8 + lrow;
                int col = k16 + (quad & 1) * 8;
                uint32_t addr = sb + SM_B + swz(row, col);
                uint32_t b0, b1, b2, b3;
                LDMX4(b0, b1, b2, b3, addr);
                #pragma unroll
                for (int mt = 0; mt < 2; mt++) {
                    MMA16816H(acc[mt][nb * 2], a[mt], b0, b1);
                    MMA16816H(acc[mt][nb * 2 + 1], a[mt], b2, b3);
                }
            }
        }
        __syncthreads();
    }

    // ---- epilogue: exact identity term from A smem (conv layers) ----
    if (IDENT) {
        #pragma unroll
        for (int mt = 0; mt < 2; mt++) {
            int row0 = wm + mt * 16 + (lane >> 2);
            int row1 = row0 + 8;
            #pragma unroll
            for (int nt = 0; nt < 8; nt++) {
                int cb = wn + nt * 8 + (lane & 3) * 2;
                __half2 h0 = *(__half2*)(smem + SM_A + swz(row0, cb));
                __half2 h1 = *(__half2*)(smem + SM_A + swz(row1, cb));
                float2 f0 = __half22float2(h0);
                float2 f1 = __half22float2(h1);
                acc[mt][nt][0] += identc * f0.x;
                acc[mt][nt][1] += identc * f0.y;
                acc[mt][nt][2] += identc * f1.x;
                acc[mt][nt][3] += identc * f1.y;
            }
        }
    }

    // ---- epilogue: store fp32 and/or fp16 ----
    #pragma unroll
    for (int mt = 0; mt < 2; mt++) {
        int r0 = block_row + wm + mt * 16 + (lane >> 2);
        int r1 = r0 + 8;
        #pragma unroll
        for (int nt = 0; nt < 8; nt++) {
            int cb = wn + nt * 8 + (lane & 3) * 2;
            float2 p0, p1;
            p0.x = acc[mt][nt][0]; p0.y = acc[mt][nt][1];
            p1.x = acc[mt][nt][2]; p1.y = acc[mt][nt][3];
            if (MODE != 1) {
                float bx = bias[cb], by = bias[cb + 1];
                p0.x += bx; p0.y += by;
                p1.x += bx; p1.y += by;
            }
            if (r0 < NN) {
                if (C)  *(float2*)(C + (long)r0 * HH + cb) = p0;
                if (Ch) *(uint32_t*)(Ch + (long)r0 * HH + cb) = pack_h2(p0.x, p0.y);
            }
            if (r1 < NN) {
                if (C)  *(float2*)(C + (long)r1 * HH + cb) = p1;
                if (Ch) *(uint32_t*)(Ch + (long)r1 * HH + cb) = pack_h2(p1.x, p1.y);
            }
        }
    }
    // ---- epilogue: fused BN statistics (after ident; padded rows = 0) ----
    if (STATS) {
        #pragma unroll
        for (int nt = 0; nt < 8; nt++) {
            #pragma unroll
            for (int p = 0; p < 2; p++) {
                float a00 = acc[0][nt][p],     a01 = acc[0][nt][2 + p];
                float a10 = acc[1][nt][p],     a11 = acc[1][nt][2 + p];
                float s = (a00 + a01) + (a10 + a11);
                float q = a00 * a00 + a01 * a01 + a10 * a10 + a11 * a11;
                #pragma unroll
                for (int m = 4; m < 32; m <<= 1) {
                    s += __shfl_xor_sync(0xFFFFFFFFu, s, m);
                    q += __shfl_xor_sync(0xFFFFFFFFu, q, m);
                }
                if (lane < 4) {
                    int cb = wn + nt * 8 + lane * 2 + p;
                    atomicAdd(&g_bnsum[statoff + cb], s);
                    atomicAdd(&g_bnsq[statoff + cb], q);
                }
            }
        }
    }
}

// ---------------- edge-list helpers ----------------------------------------
__device__ __forceinline__ int edge_at(const void* buf, int e) {
    if (g_is64) return (int)((const long long*)buf)[e];
    return ((const int*)buf)[e];
}

__global__ void detect64_k(const void* srcbuf) {
    const unsigned int* p = (const unsigned int*)srcbuf;
    int any = 0;
    for (int i = 1; i < 512; i += 2) any |= (p[i] != 0u);
    g_is64 = any ? 0 : 1;
}

// zero CSR arrays + all BN accumulator slots
__global__ void zero_all_k() {
    int i = blockIdx.x * blockDim.x + threadIdx.x;
    if (i < NN) { g_deg[i] = 0; g_cursor[i] = 0; }
    if (i < 3 * HH) { g_bnsum[i] = 0.f; g_bnsq[i] = 0.f; }
}

__global__ void hist_k(const void* dstbuf) {
    for (int e = blockIdx.x * blockDim.x + threadIdx.x; e < EE;
         e += gridDim.x * blockDim.x) {
        atomicAdd(&g_deg[edge_at(dstbuf, e)], 1);
    }
}

__global__ void scanA_k() {
    __shared__ int wt[32];
    int tid = threadIdx.x, lane = tid & 31, wid = tid >> 5;
    int i = blockIdx.x * 1024 + tid;
    int v = (i < NN) ? g_deg[i] : 0;
    int x = v;
    #pragma unroll
    for (int d = 1; d < 32; d <<= 1) {
        int y = __shfl_up_sync(0xFFFFFFFFu, x, d);
        if (lane >= d) x += y;
    }
    if (lane == 31) wt[wid] = x;
    __syncthreads();
    if (wid == 0) {
        int t = wt[lane];
        int tx = t;
        #pragma unroll
        for (int d = 1; d < 32; d <<= 1) {
            int y = __shfl_up_sync(0xFFFFFFFFu, tx, d);
            if (lane >= d) tx += y;
        }
        wt[lane] = tx - t;
    }
    __syncthreads();
    int incl = x + wt[wid];
    if (i < NN) g_rowptr[i] = incl - v;
    if (tid == 1023) g_part[blockIdx.x] = incl;
}

// parallel scan of the 98 block partials (1 block, 128 threads)
__global__ void scanB_k(int nblk) {
    __shared__ int wt[4];
    int tid = threadIdx.x, lane = tid & 31, wid = tid >> 5;
    int v = (tid < nblk) ? g_part[tid] : 0;
    int x = v;
    #pragma unroll
    for (int d = 1; d < 32; d <<= 1) {
        int y = __shfl_up_sync(0xFFFFFFFFu, x, d);
        if (lane >= d) x += y;
    }
    if (lane == 31) wt[wid] = x;
    __syncthreads();
    int woff = 0;
    for (int w = 0; w < wid; w++) woff += wt[w];
    int incl = x + woff;
    if (tid < nblk) g_partoff[tid] = incl - v;
    if (tid == 127) g_rowptr[NN] = incl;
}

__global__ void scanC_k() {
    int i = blockIdx.x * 1024 + threadIdx.x;
    if (i < NN) g_rowptr[i] += g_partoff[blockIdx.x];
}

__global__ void fill_k(const void* srcbuf, const void* dstbuf) {
    for (int e = blockIdx.x * blockDim.x + threadIdx.x; e < EE;
         e += gridDim.x * blockDim.x) {
        int d = edge_at(dstbuf, e);
        int s = edge_at(srcbuf, e);
        int pos = atomicAdd(&g_cursor[d], 1);
        g_col[g_rowptr[d] + pos] = s;
    }
}

// ------ gather: h = 0.9 * sum_src f(zh[src]) + 0.1 * x0h   (all fp16 I/O) ---
// 2 rows per warp, 16 lanes x 16B per row (LDG.128 per edge per lane).
// BNMODE 0: f = identity.  BNMODE 1: f(v) = relu(v * s[c] + t[c]).
template <int BNMODE>
__global__ void gather_k(const __half* __restrict__ zh,
                         const __half* __restrict__ x0h,
                         __half* __restrict__ h) {
    int warp = (blockIdx.x * blockDim.x + threadIdx.x) >> 5;
    int lane = threadIdx.x & 31;
    int sub = lane >> 4;       // half-warp: 0 or 1
    int sl = lane & 15;        // lane within half-warp
    int row = warp * 2 + sub;
    if (row >= NN) return;

    float s[8], t[8];
    if (BNMODE) {
        float4 sa = *(const float4*)(g_bns + sl * 8);
        float4 sb = *(const float4*)(g_bns + sl * 8 + 4);
        float4 ta = *(const float4*)(g_bnt + sl * 8);
        float4 tb = *(const float4*)(g_bnt + sl * 8 + 4);
        s[0] = sa.x; s[1] = sa.y; s[2] = sa.z; s[3] = sa.w;
        s[4] = sb.x; s[5] = sb.y; s[6] = sb.z; s[7] = sb.w;
        t[0] = ta.x; t[1] = ta.y; t[2] = ta.z; t[3] = ta.w;
        t[4] = tb.x; t[5] = tb.y; t[6] = tb.z; t[7] = tb.w;
    }

    int beg = g_rowptr[row], end = g_rowptr[row + 1];
    float acc[8];
    #pragma unroll
    for (int q = 0; q < 8; q++) acc[q] = 0.f;

    #define ACC16(u) do { \
        __half2* _h2 = (__half2*)&(u); \
        float2 _f[4]; \
        _f[0] = __half22float2(_h2[0]); _f[1] = __half22float2(_h2[1]); \
        _f[2] = __half22float2(_h2[2]); _f[3] = __half22float2(_h2[3]); \
        float _v[8] = {_f[0].x, _f[0].y, _f[1].x, _f[1].y, \
                       _f[2].x, _f[2].y, _f[3].x, _f[3].y}; \
        _Pragma("unroll") \
        for (int q = 0; q < 8; q++) { \
            float _x = _v[q]; \
            if (BNMODE) _x = fmaxf(fmaf(_x, s[q], t[q]), 0.f); \
            acc[q] += _x; \
        } } while (0)

    int e = beg;
    for (; e + 3 < end; e += 4) {
        int s0 = g_col[e], s1 = g_col[e + 1], s2 = g_col[e + 2], s3 = g_col[e + 3];
        uint4 u0 = ((const uint4*)(zh + (long)s0 * HH))[sl];
        uint4 u1 = ((const uint4*)(zh + (long)s1 * HH))[sl];
        uint4 u2 = ((const uint4*)(zh + (long)s2 * HH))[sl];
        uint4 u3 = ((const uint4*)(zh + (long)s3 * HH))[sl];
        ACC16(u0); ACC16(u1); ACC16(u2); ACC16(u3);
    }
    for (; e < end; ++e) {
        uint4 u = ((const uint4*)(zh + (long)g_col[e] * HH))[sl];
        ACC16(u);
    }
    #undef ACC16

    uint4 xu = ((const uint4*)(x0h + (long)row * HH))[sl];
    __half2* xh2 = (__half2*)&xu;
    float2 xf0 = __half22float2(xh2[0]);
    float2 xf1 = __half22float2(xh2[1]);
    float2 xf2 = __half22float2(xh2[2]);
    float2 xf3 = __half22float2(xh2[3]);
    float xv[8] = {xf0.x, xf0.y, xf1.x, xf1.y, xf2.x, xf2.y, xf3.x, xf3.y};

    uint4 o;
    uint32_t* op = &o.x;
    #pragma unroll
    for (int q = 0; q < 4; q++) {
        float a0 = 0.9f * acc[q * 2]     + 0.1f * xv[q * 2];
        float a1 = 0.9f * acc[q * 2 + 1] + 0.1f * xv[q * 2 + 1];
        op[q] = pack_h2(a0, a1);
    }
    ((uint4*)(h + (long)row * HH))[sl] = o;
}

// ---------------- BatchNorm finalize ----------------------------------------
__global__ void finalize_bn_k(const float* __restrict__ gamma,
                              const float* __restrict__ beta, int statoff) {
    int c = threadIdx.x;
    float invN = 1.0f / (float)NN;
    float m = g_bnsum[statoff + c] * invN;
    float var = g_bnsq[statoff + c] * invN - m * m;
    float s = rsqrtf(var + 1e-5f) * gamma[c];
    g_bns[c] = s;
    g_bnt[c] = beta[c] - m * s;
}

// ---------------- host orchestration ----------------------------------------
extern "C" void kernel_launch(void* const* d_in, const int* in_sizes, int n_in,
                              void* d_out, int out_size) {
    const float* x     = (const float*)d_in[0];
    const float* W_in  = (const float*)d_in[1];
    const float* b_in  = (const float*)d_in[2];
    const float* convW = (const float*)d_in[3];
    const float* gma   = (const float*)d_in[4];
    const float* bta   = (const float*)d_in[5];
    const float* W_jk  = (const float*)d_in[6];
    const float* b_jk  = (const float*)d_in[7];
    const void*  src   = d_in[8];
    const void*  dst   = d_in[9];
    float* out = (float*)d_out;

    void *ph, *pzh;
    cudaGetSymbolAddress(&ph, g_h);
    cudaGetSymbolAddress(&pzh, g_zh);
    __half* h   = (__half*)ph;
    __half* zh0 = (__half*)pzh;
    __half* zh1 = zh0 + (long)NN * HH;
    __half* zh2 = zh1 + (long)NN * HH;
    __half* zh3 = zh2 + (long)NN * HH;
    __half* zh4 = zh3 + (long)NN * HH;
    __half* zh5 = zh4 + (long)NN * HH;

    float bl[LL];
    for (int i = 0; i < LL; i++) bl[i] = (float)log(0.5 / (double)(i + 1) + 1.0);

    cudaFuncSetAttribute(gemm_tc_k<0, 0, 0, 0>, cudaFuncAttributeMaxDynamicSharedMemorySize, SM_TOTAL);
    cudaFuncSetAttribute(gemm_tc_k<1, 0, 1, 1>, cudaFuncAttributeMaxDynamicSharedMemorySize, SM_TOTAL);
    cudaFuncSetAttribute(gemm_tc_k<1, 1, 1, 1>, cudaFuncAttributeMaxDynamicSharedMemorySize, SM_TOTAL);
    cudaFuncSetAttribute(gemm_tc_k<2, 0, 0, 1>, cudaFuncAttributeMaxDynamicSharedMemorySize, SM_TOTAL);

    const int GEMM_BLOCKS = (NN + 127) / 128;            // 782
    const int GATHER_BLOCKS = ((NN + 1) / 2 * 32 + 255) / 256;
    const int SCAN_BLOCKS = (NN + 1023) / 1024;          // 98

    // ---- forked side stream: CSR build concurrent with prep + input GEMM ----
    cudaStream_t s2;
    cudaStreamCreateWithFlags(&s2, cudaStreamNonBlocking);
    cudaEvent_t evFork, evJoin;
    cudaEventCreateWithFlags(&evFork, cudaEventDisableTiming);
    cudaEventCreateWithFlags(&evJoin, cudaEventDisableTiming);

    cudaEventRecord(evFork, 0);
    cudaStreamWaitEvent(s2, evFork, 0);

    zero_all_k<<<(NN + 255) / 256, 256, 0, s2>>>();
    detect64_k<<<1, 1, 0, s2>>>(src);
    hist_k<<<1024, 256, 0, s2>>>(dst);
    scanA_k<<<SCAN_BLOCKS, 1024, 0, s2>>>();
    scanB_k<<<1, 128, 0, s2>>>(SCAN_BLOCKS);
    scanC_k<<<SCAN_BLOCKS, 1024, 0, s2>>>();
    fill_k<<<1024, 256, 0, s2>>>(src, dst);
    cudaEventRecord(evJoin, s2);

    // main stream: B prep + input GEMM (fp32 A, converts in fill)
    prep_b_k<<<10, 256>>>(W_in, convW, W_jk, bl[0], bl[1], bl[2], bl[3], bl[4]);
    gemm_tc_k<0, 0, 0, 0><<<GEMM_BLOCKS, 256, SM_TOTAL>>>(x, 0, 0, 0, b_in, 0,
                                                          0.f, 0, 0, zh0);

    cudaStreamWaitEvent(0, evJoin, 0);

    const __half* gin[LL]  = {zh0, zh1, zh2, zh3, zh5};
    __half* chout[LL]      = {zh1, zh2, zh3, zh4, 0};
    for (int i = 0; i < LL; i++) {
        if (i >= 1 && i <= 3)
            gather_k<1><<<GATHER_BLOCKS, 256>>>(gin[i], zh0, h);
        else
            gather_k<0><<<GATHER_BLOCKS, 256>>>(gin[i], zh0, h);
        float* Cout = (i == 4) ? out : 0;
        float identc = 1.0f - bl[i];
        if (i < 3) {
            gemm_tc_k<1, 1, 1, 1><<<GEMM_BLOCKS, 256, SM_TOTAL>>>(
                h, 0, 0, 0, 0, 1 + i, identc, i * HH, Cout, chout[i]);
            finalize_bn_k<<<1, HH>>>(gma + i * HH, bta + i * HH, i * HH);
        } else {
            gemm_tc_k<1, 0, 1, 1><<<GEMM_BLOCKS, 256, SM_TOTAL>>>(
                h, 0, 0, 0, 0, 1 + i, identc, 0, Cout, chout[i]);
        }
        if (i == 3) {
            gemm_tc_k<2, 0, 0, 1><<<GEMM_BLOCKS, 256, SM_TOTAL>>>(
                zh1, zh2, zh3, zh4, b_jk, 6, 0.f, 0, 0, zh5);
        }
    }

    cudaEventDestroy(evFork);
    cudaEventDestroy(evJoin);
    cudaStreamDestroy(s2);
    (void)in_sizes; (void)n_in; (void)out_size;
}

// round 17
// speedup vs baseline: 1.0472x; 1.0438x over previous
#include <cuda_runtime.h>
#include <cuda_fp16.h>
#include <math.h>
#include <stdint.h>

#define NN 100000
#define EE 1600000
#define HH 128
#define LL 5

// ---------------- device scratch (static; no allocations allowed) ----------
// fp16 activation slots: 0=input-layer out (x0), 1..4=conv0..3 out, 5=JK out
__device__ __align__(16) __half g_zh[6 * NN * HH];
__device__ __align__(16) __half g_h[NN * HH];       // gather output
__device__ __align__(16) uint8_t g_B[10 * 32768];   // fp16 W tiles (swizzled)
__device__ int   g_deg[NN];
__device__ int   g_rowptr[NN + 1];
__device__ int   g_cursor[NN];
__device__ int   g_col[EE];
__device__ int   g_is64;
__device__ int   g_part[128];
__device__ int   g_partoff[128];
__device__ float g_bnsum[3 * HH];   // per-layer slots, zeroed once in prologue
__device__ float g_bnsq[3 * HH];
__device__ float g_bns[HH];
__device__ float g_bnt[HH];

// ---------------- helpers ---------------------------------------------------
__device__ __forceinline__ uint32_t smem_u32(const void* p) {
    uint32_t a;
    asm("{ .reg .u64 t; cvta.to.shared.u64 t, %1; cvt.u32.u64 %0, t; }"
        : "=r"(a) : "l"(p));
    return a;
}

static __device__ __forceinline__ uint32_t pack_h2(float a, float b) {
    __half2 t = __floats2half2_rn(a, b);
    return *(uint32_t*)&t;
}

// XOR-swizzled byte offset inside a (rows x 128) fp16 tile (pitch 256B).
__device__ __forceinline__ int swz(int row, int col) {
    return row * 256 + ((((col >> 3) ^ (row & 7)) & 15) << 4) + ((col & 7) << 1);
}

#define LDMX4(r0, r1, r2, r3, addr) \
    asm volatile("ldmatrix.sync.aligned.m8n8.x4.shared.b16 {%0,%1,%2,%3}, [%4];" \
                 : "=r"(r0), "=r"(r1), "=r"(r2), "=r"(r3) : "r"(addr))

#define MMA16816H(c, a, b0, b1) \
    asm volatile( \
        "mma.sync.aligned.m16n8k16.row.col.f32.f16.f16.f32 " \
        "{%0,%1,%2,%3}, {%4,%5,%6,%7}, {%8,%9}, {%0,%1,%2,%3};" \
        : "+f"((c)[0]), "+f"((c)[1]), "+f"((c)[2]), "+f"((c)[3]) \
        : "r"((a)[0]), "r"((a)[1]), "r"((a)[2]), "r"((a)[3]), "r"(b0), "r"(b1))

// SMEM: A fp16 128x128 (32KB) + B fp16 (32KB) = 64KB
#define SM_A 0
#define SM_B 32768
#define SM_TOTAL 65536

// ---------------- B-tile preparation (once per launch) ----------------------
__global__ __launch_bounds__(256) void prep_b_k(
    const float* __restrict__ W_in, const float* __restrict__ convW,
    const float* __restrict__ W_jk,
    float b0, float b1, float b2, float b3, float b4) {
    int t = blockIdx.x;
    const float* W;
    float wscale;
    if (t == 0) { W = W_in; wscale = 1.f; }
    else if (t <= 5) {
        float blv = (t == 1) ? b0 : (t == 2) ? b1 : (t == 3) ? b2 : (t == 4) ? b3 : b4;
        W = convW + (long)(t - 1) * HH * HH;
        wscale = blv;
    } else { W = W_jk + (long)(t - 6) * HH * HH; wscale = 1.f; }

    int tid = threadIdx.x;
    int n = tid >> 1;
    int kb = (tid & 1) << 6;
    const float* Wb = W + (long)kb * HH + n;
    uint8_t* bp = g_B + (long)t * 32768;
    #pragma unroll
    for (int jj = 0; jj < 8; jj++) {
        int k0 = kb + jj * 8;
        uint4 hv;
        uint32_t* hp = &hv.x;
        #pragma unroll
        for (int q = 0; q < 4; q++) {
            float w0 = wscale * Wb[(long)(jj * 8 + q * 2) * HH];
            float w1 = wscale * Wb[(long)(jj * 8 + q * 2 + 1) * HH];
            hp[q] = pack_h2(w0, w1);
        }
        *(uint4*)(bp + swz(n, k0)) = hv;
    }
}

// ---------------- tensor-core GEMM (fp16 A, fp16 W, 1 term) -----------------
// MODE 0: single chunk +bias (A fp32 if HALFA=0).  MODE 1: plain conv.
// MODE 2: 4 chunks +bias.  IDENT 1: epilogue adds identc*h from A smem.
// STATS 1: atomicAdd col stats of final C into g_bnsum/g_bnsq at statoff.
template <int MODE, int STATS, int IDENT, int HALFA>
__global__ __launch_bounds__(256, 2) void gemm_tc_k(
    const void* __restrict__ A0, const void* __restrict__ A1,
    const void* __restrict__ A2, const void* __restrict__ A3,
    const float* __restrict__ bias, int tbase, float identc, int statoff,
    float* __restrict__ C, __half* __restrict__ Ch) {
    extern __shared__ char smem[];
    uint32_t sb = smem_u32(smem);
    const int tid = threadIdx.x;
    const int wid = tid >> 5, lane = tid & 31;
    const int block_row = blockIdx.x * 128;

    const int wm = (wid & 3) * 32;
    const int wn = (wid >> 2) * 64;
    const int lrow = lane & 7, quad = lane >> 3;

    float acc[2][8][4];
    #pragma unroll
    for (int i = 0; i < 2; i++)
        #pragma unroll
        for (int j = 0; j < 8; j++)
            #pragma unroll
            for (int q = 0; q < 4; q++) acc[i][j][q] = 0.f;

    const int NCH = (MODE == 2) ? 4 : 1;
    for (int c = 0; c < NCH; c++) {
        const void* Ab = (c == 0) ? A0 : (c == 1) ? A1 : (c == 2) ? A2 : A3;
        // ---- A tile fill ----
        {
            int row = tid >> 1;
            int cb = (tid & 1) << 6;
            int grow = block_row + row;
            #pragma unroll
            for (int jj = 0; jj < 8; jj++) {
                uint4 u = make_uint4(0u, 0u, 0u, 0u);
                if (grow < NN) {
                    if (HALFA) {
                        u = ((const uint4*)((const __half*)Ab + (long)grow * HH + cb))[jj];
                    } else {
                        const float4* sp = (const float4*)((const float*)Ab +
                                            (long)grow * HH + cb);
                        float4 v0 = sp[jj * 2], v1 = sp[jj * 2 + 1];
                        u.x = pack_h2(v0.x, v0.y);
                        u.y = pack_h2(v0.z, v0.w);
                        u.z = pack_h2(v1.x, v1.y);
                        u.w = pack_h2(v1.z, v1.w);
                    }
                }
                *(uint4*)(smem + SM_A + swz(row, cb + jj * 8)) = u;
            }
        }
        // ---- B tile fill: straight copy of preconverted swizzled image ----
        {
            const uint4* bsrc = (const uint4*)(g_B + (long)(tbase + c) * 32768);
            uint4* bdst = (uint4*)(smem + SM_B);
            #pragma unroll
            for (int s = tid; s < 2048; s += 256) bdst[s] = bsrc[s];
        }
        __syncthreads();

        // ---- compute: single fp16 term ----
        #pragma unroll
        for (int k16 = 0; k16 < 128; k16 += 16) {
            uint32_t a[2][4];
            #pragma unroll
            for (int mt = 0; mt < 2; mt++) {
                int row = wm + mt * 16 + (quad & 1) * 8 + lrow;
                int col = k16 + (quad >> 1) * 8;
                uint32_t addr = sb + SM_A + swz(row, col);
                LDMX4(a[mt][0], a[mt][1], a[mt][2], a[mt][3], addr);
            }
            #pragma unroll
            for (int nb = 0; nb < 4; nb++) {
                int row = wn + nb * 16 + (quad >> 1) * 8 + lrow;
                int col = k16 + (quad & 1) * 8;
                uint32_t addr = sb + SM_B + swz(row, col);
                uint32_t b0, b1, b2, b3;
                LDMX4(b0, b1, b2, b3, addr);
                #pragma unroll
                for (int mt = 0; mt < 2; mt++) {
                    MMA16816H(acc[mt][nb * 2], a[mt], b0, b1);
                    MMA16816H(acc[mt][nb * 2 + 1], a[mt], b2, b3);
                }
            }
        }
        __syncthreads();
    }

    // ---- epilogue: exact identity term from A smem (conv layers) ----
    if (IDENT) {
        #pragma unroll
        for (int mt = 0; mt < 2; mt++) {
            int row0 = wm + mt * 16 + (lane >> 2);
            int row1 = row0 + 8;
            #pragma unroll
            for (int nt = 0; nt < 8; nt++) {
                int cb = wn + nt * 8 + (lane & 3) * 2;
                __half2 h0 = *(__half2*)(smem + SM_A + swz(row0, cb));
                __half2 h1 = *(__half2*)(smem + SM_A + swz(row1, cb));
                float2 f0 = __half22float2(h0);
                float2 f1 = __half22float2(h1);
                acc[mt][nt][0] += identc * f0.x;
                acc[mt][nt][1] += identc * f0.y;
                acc[mt][nt][2] += identc * f1.x;
                acc[mt][nt][3] += identc * f1.y;
            }
        }
    }

    // ---- epilogue: store fp32 and/or fp16 ----
    #pragma unroll
    for (int mt = 0; mt < 2; mt++) {
        int r0 = block_row + wm + mt * 16 + (lane >> 2);
        int r1 = r0 + 8;
        #pragma unroll
        for (int nt = 0; nt < 8; nt++) {
            int cb = wn + nt * 8 + (lane & 3) * 2;
            float2 p0, p1;
            p0.x = acc[mt][nt][0]; p0.y = acc[mt][nt][1];
            p1.x = acc[mt][nt][2]; p1.y = acc[mt][nt][3];
            if (MODE != 1) {
                float bx = bias[cb], by = bias[cb + 1];
                p0.x += bx; p0.y += by;
                p1.x += bx; p1.y += by;
            }
            if (r0 < NN) {
                if (C)  *(float2*)(C + (long)r0 * HH + cb) = p0;
                if (Ch) *(uint32_t*)(Ch + (long)r0 * HH + cb) = pack_h2(p0.x, p0.y);
            }
            if (r1 < NN) {
                if (C)  *(float2*)(C + (long)r1 * HH + cb) = p1;
                if (Ch) *(uint32_t*)(Ch + (long)r1 * HH + cb) = pack_h2(p1.x, p1.y);
            }
        }
    }
    // ---- epilogue: fused BN statistics (after ident; padded rows = 0) ----
    if (STATS) {
        #pragma unroll
        for (int nt = 0; nt < 8; nt++) {
            #pragma unroll
            for (int p = 0; p < 2; p++) {
                float a00 = acc[0][nt][p],     a01 = acc[0][nt][2 + p];
                float a10 = acc[1][nt][p],     a11 = acc[1][nt][2 + p];
                float s = (a00 + a01) + (a10 + a11);
                float q = a00 * a00 + a01 * a01 + a10 * a10 + a11 * a11;
                #pragma unroll
                for (int m = 4; m < 32; m <<= 1) {
                    s += __shfl_xor_sync(0xFFFFFFFFu, s, m);
                    q += __shfl_xor_sync(0xFFFFFFFFu, q, m);
                }
                if (lane < 4) {
                    int cb = wn + nt * 8 + lane * 2 + p;
                    atomicAdd(&g_bnsum[statoff + cb], s);
                    atomicAdd(&g_bnsq[statoff + cb], q);
                }
            }
        }
    }
}

// ---------------- edge-list helpers ----------------------------------------
__device__ __forceinline__ int edge_at(const void* buf, int e) {
    if (g_is64) return (int)((const long long*)buf)[e];
    return ((const int*)buf)[e];
}

__global__ void detect64_k(const void* srcbuf) {
    const unsigned int* p = (const unsigned int*)srcbuf;
    int any = 0;
    for (int i = 1; i < 512; i += 2) any |= (p[i] != 0u);
    g_is64 = any ? 0 : 1;
}

// zero CSR arrays + all BN accumulator slots
__global__ void zero_all_k() {
    int i = blockIdx.x * blockDim.x + threadIdx.x;
    if (i < NN) { g_deg[i] = 0; g_cursor[i] = 0; }
    if (i < 3 * HH) { g_bnsum[i] = 0.f; g_bnsq[i] = 0.f; }
}

__global__ void hist_k(const void* dstbuf) {
    for (int e = blockIdx.x * blockDim.x + threadIdx.x; e < EE;
         e += gridDim.x * blockDim.x) {
        atomicAdd(&g_deg[edge_at(dstbuf, e)], 1);
    }
}

__global__ void scanA_k() {
    __shared__ int wt[32];
    int tid = threadIdx.x, lane = tid & 31, wid = tid >> 5;
    int i = blockIdx.x * 1024 + tid;
    int v = (i < NN) ? g_deg[i] : 0;
    int x = v;
    #pragma unroll
    for (int d = 1; d < 32; d <<= 1) {
        int y = __shfl_up_sync(0xFFFFFFFFu, x, d);
        if (lane >= d) x += y;
    }
    if (lane == 31) wt[wid] = x;
    __syncthreads();
    if (wid == 0) {
        int t = wt[lane];
        int tx = t;
        #pragma unroll
        for (int d = 1; d < 32; d <<= 1) {
            int y = __shfl_up_sync(0xFFFFFFFFu, tx, d);
            if (lane >= d) tx += y;
        }
        wt[lane] = tx - t;
    }
    __syncthreads();
    int incl = x + wt[wid];
    if (i < NN) g_rowptr[i] = incl - v;
    if (tid == 1023) g_part[blockIdx.x] = incl;
}

// parallel scan of the 98 block partials (1 block, 128 threads)
__global__ void scanB_k(int nblk) {
    __shared__ int wt[4];
    int tid = threadIdx.x, lane = tid & 31, wid = tid >> 5;
    int v = (tid < nblk) ? g_part[tid] : 0;
    int x = v;
    #pragma unroll
    for (int d = 1; d < 32; d <<= 1) {
        int y = __shfl_up_sync(0xFFFFFFFFu, x, d);
        if (lane >= d) x += y;
    }
    if (lane == 31) wt[wid] = x;
    __syncthreads();
    int woff = 0;
    for (int w = 0; w < wid; w++) woff += wt[w];
    int incl = x + woff;
    if (tid < nblk) g_partoff[tid] = incl - v;
    if (tid == 127) g_rowptr[NN] = incl;
}

__global__ void scanC_k() {
    int i = blockIdx.x * 1024 + threadIdx.x;
    if (i < NN) g_rowptr[i] += g_partoff[blockIdx.x];
}

__global__ void fill_k(const void* srcbuf, const void* dstbuf) {
    for (int e = blockIdx.x * blockDim.x + threadIdx.x; e < EE;
         e += gridDim.x * blockDim.x) {
        int d = edge_at(dstbuf, e);
        int s = edge_at(srcbuf, e);
        int pos = atomicAdd(&g_cursor[d], 1);
        g_col[g_rowptr[d] + pos] = s;
    }
}

// ------ gather: h = 0.9 * sum_src f(zh[src]) + 0.1 * x0h   (all fp16 I/O) ---
// One row per warp (uniform trip counts), 8B per lane.  (round-14 proven)
// BNMODE 0: f = identity.  BNMODE 1: f(v) = relu(v * s[c] + t[c]).
template <int BNMODE>
__global__ void gather_k(const __half* __restrict__ zh,
                         const __half* __restrict__ x0h,
                         __half* __restrict__ h) {
    int gw = (blockIdx.x * blockDim.x + threadIdx.x) >> 5;
    if (gw >= NN) return;
    int lane = threadIdx.x & 31;
    float4 s4, t4;
    if (BNMODE) {
        s4 = *(const float4*)(g_bns + lane * 4);
        t4 = *(const float4*)(g_bnt + lane * 4);
    }
    int beg = g_rowptr[gw], end = g_rowptr[gw + 1];
    float4 acc = make_float4(0.f, 0.f, 0.f, 0.f);
    int e = beg;
    #define LD4H(v, p, s) do { \
        uint2 _u = ((const uint2*)((p) + (long)(s) * HH))[lane]; \
        float2 _f01 = __half22float2(*(__half2*)&_u.x); \
        float2 _f23 = __half22float2(*(__half2*)&_u.y); \
        (v).x = _f01.x; (v).y = _f01.y; (v).z = _f23.x; (v).w = _f23.y; } while (0)
    #define XF(v) do { if (BNMODE) { \
        (v).x = fmaxf(fmaf((v).x, s4.x, t4.x), 0.f); \
        (v).y = fmaxf(fmaf((v).y, s4.y, t4.y), 0.f); \
        (v).z = fmaxf(fmaf((v).z, s4.z, t4.z), 0.f); \
        (v).w = fmaxf(fmaf((v).w, s4.w, t4.w), 0.f); } } while (0)
    for (; e + 3 < end; e += 4) {
        int s0 = g_col[e], s1 = g_col[e + 1], s2 = g_col[e + 2], s3 = g_col[e + 3];
        float4 v0, v1, v2, v3;
        LD4H(v0, zh, s0); LD4H(v1, zh, s1); LD4H(v2, zh, s2); LD4H(v3, zh, s3);
        XF(v0); XF(v1); XF(v2); XF(v3);
        acc.x += (v0.x + v1.x) + (v2.x + v3.x);
        acc.y += (v0.y + v1.y) + (v2.y + v3.y);
        acc.z += (v0.z + v1.z) + (v2.z + v3.z);
        acc.w += (v0.w + v1.w) + (v2.w + v3.w);
    }
    for (; e < end; ++e) {
        int s = g_col[e];
        float4 v;
        LD4H(v, zh, s);
        XF(v);
        acc.x += v.x; acc.y += v.y; acc.z += v.z; acc.w += v.w;
    }
    float4 xv;
    LD4H(xv, x0h, gw);
    #undef XF
    #undef LD4H
    const float A1 = 0.9f, A0 = 0.1f;
    float ox = A1 * acc.x + A0 * xv.x;
    float oy = A1 * acc.y + A0 * xv.y;
    float oz = A1 * acc.z + A0 * xv.z;
    float ow = A1 * acc.w + A0 * xv.w;
    uint2 o;
    o.x = pack_h2(ox, oy);
    o.y = pack_h2(oz, ow);
    ((uint2*)(h + (long)gw * HH))[lane] = o;
}

// ---------------- BatchNorm finalize ----------------------------------------
__global__ void finalize_bn_k(const float* __restrict__ gamma,
                              const float* __restrict__ beta, int statoff) {
    int c = threadIdx.x;
    float invN = 1.0f / (float)NN;
    float m = g_bnsum[statoff + c] * invN;
    float var = g_bnsq[statoff + c] * invN - m * m;
    float s = rsqrtf(var + 1e-5f) * gamma[c];
    g_bns[c] = s;
    g_bnt[c] = beta[c] - m * s;
}

// ---------------- host orchestration ----------------------------------------
extern "C" void kernel_launch(void* const* d_in, const int* in_sizes, int n_in,
                              void* d_out, int out_size) {
    const float* x     = (const float*)d_in[0];
    const float* W_in  = (const float*)d_in[1];
    const float* b_in  = (const float*)d_in[2];
    const float* convW = (const float*)d_in[3];
    const float* gma   = (const float*)d_in[4];
    const float* bta   = (const float*)d_in[5];
    const float* W_jk  = (const float*)d_in[6];
    const float* b_jk  = (const float*)d_in[7];
    const void*  src   = d_in[8];
    const void*  dst   = d_in[9];
    float* out = (float*)d_out;

    void *ph, *pzh;
    cudaGetSymbolAddress(&ph, g_h);
    cudaGetSymbolAddress(&pzh, g_zh);
    __half* h   = (__half*)ph;
    __half* zh0 = (__half*)pzh;
    __half* zh1 = zh0 + (long)NN * HH;
    __half* zh2 = zh1 + (long)NN * HH;
    __half* zh3 = zh2 + (long)NN * HH;
    __half* zh4 = zh3 + (long)NN * HH;
    __half* zh5 = zh4 + (long)NN * HH;

    float bl[LL];
    for (int i = 0; i < LL; i++) bl[i] = (float)log(0.5 / (double)(i + 1) + 1.0);

    cudaFuncSetAttribute(gemm_tc_k<0, 0, 0, 0>, cudaFuncAttributeMaxDynamicSharedMemorySize, SM_TOTAL);
    cudaFuncSetAttribute(gemm_tc_k<1, 0, 1, 1>, cudaFuncAttributeMaxDynamicSharedMemorySize, SM_TOTAL);
    cudaFuncSetAttribute(gemm_tc_k<1, 1, 1, 1>, cudaFuncAttributeMaxDynamicSharedMemorySize, SM_TOTAL);
    cudaFuncSetAttribute(gemm_tc_k<2, 0, 0, 1>, cudaFuncAttributeMaxDynamicSharedMemorySize, SM_TOTAL);

    const int GEMM_BLOCKS = (NN + 127) / 128;            // 782
    const int GATHER_BLOCKS = (NN * 32 + 255) / 256;
    const int SCAN_BLOCKS = (NN + 1023) / 1024;          // 98

    // ---- forked side stream: CSR build concurrent with prep + input GEMM ----
    cudaStream_t s2;
    cudaStreamCreateWithFlags(&s2, cudaStreamNonBlocking);
    cudaEvent_t evFork, evJoin;
    cudaEventCreateWithFlags(&evFork, cudaEventDisableTiming);
    cudaEventCreateWithFlags(&evJoin, cudaEventDisableTiming);

    cudaEventRecord(evFork, 0);
    cudaStreamWaitEvent(s2, evFork, 0);

    zero_all_k<<<(NN + 255) / 256, 256, 0, s2>>>();
    detect64_k<<<1, 1, 0, s2>>>(src);
    hist_k<<<1024, 256, 0, s2>>>(dst);
    scanA_k<<<SCAN_BLOCKS, 1024, 0, s2>>>();
    scanB_k<<<1, 128, 0, s2>>>(SCAN_BLOCKS);
    scanC_k<<<SCAN_BLOCKS, 1024, 0, s2>>>();
    fill_k<<<1024, 256, 0, s2>>>(src, dst);
    cudaEventRecord(evJoin, s2);

    // main stream: B prep + input GEMM (fp32 A, converts in fill)
    prep_b_k<<<10, 256>>>(W_in, convW, W_jk, bl[0], bl[1], bl[2], bl[3], bl[4]);
    gemm_tc_k<0, 0, 0, 0><<<GEMM_BLOCKS, 256, SM_TOTAL>>>(x, 0, 0, 0, b_in, 0,
                                                          0.f, 0, 0, zh0);

    cudaStreamWaitEvent(0, evJoin, 0);

    const __half* gin[LL]  = {zh0, zh1, zh2, zh3, zh5};
    __half* chout[LL]      = {zh1, zh2, zh3, zh4, 0};
    for (int i = 0; i < LL; i++) {
        if (i >= 1 && i <= 3)
            gather_k<1><<<GATHER_BLOCKS, 256>>>(gin[i], zh0, h);
        else
            gather_k<0><<<GATHER_BLOCKS, 256>>>(gin[i], zh0, h);
        float* Cout = (i == 4) ? out : 0;
        float identc = 1.0f - bl[i];
        if (i < 3) {
            gemm_tc_k<1, 1, 1, 1><<<GEMM_BLOCKS, 256, SM_TOTAL>>>(
                h, 0, 0, 0, 0, 1 + i, identc, i * HH, Cout, chout[i]);
            finalize_bn_k<<<1, HH>>>(gma + i * HH, bta + i * HH, i * HH);
        } else {
            gemm_tc_k<1, 0, 1, 1><<<GEMM_BLOCKS, 256, SM_TOTAL>>>(
                h, 0, 0, 0, 0, 1 + i, identc, 0, Cout, chout[i]);
        }
        if (i == 3) {
            gemm_tc_k<2, 0, 0, 1><<<GEMM_BLOCKS, 256, SM_TOTAL>>>(
                zh1, zh2, zh3, zh4, b_jk, 6, 0.f, 0, 0, zh5);
        }
    }

    cudaEventDestroy(evFork);
    cudaEventDestroy(evJoin);
    cudaStreamDestroy(s2);
    (void)in_sizes; (void)n_in; (void)out_size;
}